// round 3
// baseline (speedup 1.0000x reference)
#include <cuda_runtime.h>
#include <math.h>

// ---------------------------------------------------------------------------
// EfficientFrequencyAttention  B=8, C=256, H=W=64
// ---------------------------------------------------------------------------
#define Bn  8
#define Cn  256
#define Hn  64
#define Wn  64
#define HWn 4096          // Hn*Wn
#define BCHW (Bn*Cn*HWn)  // 8,388,608
#define BCC  (Bn*Cn*Cn)   // 524,288

// ----------------------------- scratch (static, no allocation) -------------
__device__ float g_K   [BCHW];
__device__ float g_Q   [BCHW];
__device__ float g_V   [BCHW];
__device__ float g_G1  [BCHW];
__device__ float g_G2  [BCHW];
__device__ float g_S   [BCHW];
__device__ float g_Atd [BCHW];   // attended
__device__ float g_Ctx [BCC];
__device__ float g_Gram[BCC];
__device__ float g_Attm[BCC];    // accumulated channel attention

// ---------------------------------------------------------------------------
// 1x1 conv:  Y[b,k,n] = sum_c W[k,c] * X[b,c,n] + bias[k]
// grid (HW/64, C/64, B), block 256, 64x64 tile, 4x4 microtile
// ---------------------------------------------------------------------------
__global__ __launch_bounds__(256)
void conv1x1_kernel(const float* __restrict__ X, const float* __restrict__ Wm,
                    const float* __restrict__ bias, float* __restrict__ Y)
{
    __shared__ float Ws[16][65];   // Ws[c][k]  (transposed W tile)
    __shared__ float Xs[16][64];   // Xs[c][n]

    const int b  = blockIdx.z;
    const int k0 = blockIdx.y * 64;
    const int n0 = blockIdx.x * 64;
    const int t  = threadIdx.x;
    const int tx = t & 15, ty = t >> 4;

    const float* Xb = X + (size_t)b * Cn * HWn;
    float acc[4][4] = {};

    for (int c0 = 0; c0 < Cn; c0 += 16) {
        #pragma unroll
        for (int r = 0; r < 4; r++) {                 // W tile: 64k x 16c
            int e = t + r * 256;
            int kk = e >> 4, cc = e & 15;
            Ws[cc][kk] = Wm[(size_t)(k0 + kk) * Cn + c0 + cc];
        }
        #pragma unroll
        for (int r = 0; r < 4; r++) {                 // X tile: 16c x 64n
            int e = t + r * 256;
            int cc = e >> 6, nn = e & 63;
            Xs[cc][nn] = Xb[(size_t)(c0 + cc) * HWn + n0 + nn];
        }
        __syncthreads();
        #pragma unroll
        for (int cc = 0; cc < 16; cc++) {
            float w[4];
            #pragma unroll
            for (int i = 0; i < 4; i++) w[i] = Ws[cc][ty * 4 + i];
            float4 xv = *(const float4*)&Xs[cc][tx * 4];
            float xs[4] = {xv.x, xv.y, xv.z, xv.w};
            #pragma unroll
            for (int i = 0; i < 4; i++)
                #pragma unroll
                for (int j = 0; j < 4; j++)
                    acc[i][j] += w[i] * xs[j];
        }
        __syncthreads();
    }

    float* Yb = Y + (size_t)b * Cn * HWn;
    #pragma unroll
    for (int i = 0; i < 4; i++) {
        int k = k0 + ty * 4 + i;
        float bv = bias[k];
        float4 o;
        o.x = acc[i][0] + bv; o.y = acc[i][1] + bv;
        o.z = acc[i][2] + bv; o.w = acc[i][3] + bv;
        *(float4*)&Yb[(size_t)k * HWn + n0 + tx * 4] = o;
    }
}

// ---------------------------------------------------------------------------
// softmax over HW (4096) per (b,c) row; input may be A or (A - Bm)
// grid = B*C (2048), block 256, 16 values/thread, in-place safe
// ---------------------------------------------------------------------------
__global__ __launch_bounds__(256)
void softmax_hw_kernel(const float* __restrict__ A, const float* __restrict__ Bm,
                       float* __restrict__ out, int hasB)
{
    __shared__ float red[256];
    const size_t base = (size_t)blockIdx.x * HWn;
    const int t = threadIdx.x;

    float v[16];
    float m = -INFINITY;
    #pragma unroll
    for (int i = 0; i < 16; i++) {
        size_t idx = base + t + i * 256;
        float a = A[idx];
        if (hasB) a -= Bm[idx];
        v[i] = a;
        m = fmaxf(m, a);
    }
    red[t] = m; __syncthreads();
    for (int s = 128; s > 0; s >>= 1) {
        if (t < s) red[t] = fmaxf(red[t], red[t + s]);
        __syncthreads();
    }
    m = red[0]; __syncthreads();

    float sum = 0.f;
    #pragma unroll
    for (int i = 0; i < 16; i++) { v[i] = expf(v[i] - m); sum += v[i]; }
    red[t] = sum; __syncthreads();
    for (int s = 128; s > 0; s >>= 1) {
        if (t < s) red[t] += red[t + s];
        __syncthreads();
    }
    float inv = 1.0f / red[0];
    #pragma unroll
    for (int i = 0; i < 16; i++) out[base + t + i * 256] = v[i] * inv;
}

// ---------------------------------------------------------------------------
// softmax over channel axis (256) per (b,n) column, in-place
// grid = B*HW/256 (128), block 256
// ---------------------------------------------------------------------------
__global__ __launch_bounds__(256)
void softmax_c_kernel(float* __restrict__ Q)
{
    const int col = blockIdx.x * 256 + threadIdx.x;   // 0..B*HW-1
    const int b = col >> 12;
    const int n = col & 4095;
    float* p = Q + (size_t)b * Cn * HWn + n;

    float m = -INFINITY;
    for (int c = 0; c < Cn; c++) m = fmaxf(m, p[(size_t)c * HWn]);
    float s = 0.f;
    for (int c = 0; c < Cn; c++) s += expf(p[(size_t)c * HWn] - m);
    float inv = 1.0f / s;
    for (int c = 0; c < Cn; c++) {
        size_t idx = (size_t)c * HWn;
        p[idx] = expf(p[idx] - m) * inv;
    }
}

// ---------------------------------------------------------------------------
// gram (NT):  A[b,i,j] = sum_n S[b,i,n] * (LA[b,j,n] - LB[b,j,n]?)
// grid (4,4,B), block 256
// ---------------------------------------------------------------------------
__global__ __launch_bounds__(256)
void gram_kernel(const float* __restrict__ S, const float* __restrict__ LA,
                 const float* __restrict__ LB, float* __restrict__ A, int hasB)
{
    __shared__ float Ss[32][65];   // Ss[n][i]
    __shared__ float Ls[32][65];   // Ls[n][j]

    const int b  = blockIdx.z;
    const int i0 = blockIdx.y * 64;
    const int j0 = blockIdx.x * 64;
    const int t  = threadIdx.x;
    const int tx = t & 15, ty = t >> 4;

    const float* Sb  = S  + (size_t)b * Cn * HWn;
    const float* LAb = LA + (size_t)b * Cn * HWn;
    const float* LBb = hasB ? (LB + (size_t)b * Cn * HWn) : LA;

    float acc[4][4] = {};

    for (int n0 = 0; n0 < HWn; n0 += 32) {
        #pragma unroll
        for (int r = 0; r < 8; r++) {
            int e = t + r * 256;           // 0..2047 over 64 rows x 32 n
            int row = e >> 5, nn = e & 31;
            Ss[nn][row] = Sb[(size_t)(i0 + row) * HWn + n0 + nn];
            float lv = LAb[(size_t)(j0 + row) * HWn + n0 + nn];
            if (hasB) lv -= LBb[(size_t)(j0 + row) * HWn + n0 + nn];
            Ls[nn][row] = lv;
        }
        __syncthreads();
        #pragma unroll
        for (int nn = 0; nn < 32; nn++) {
            float sv[4], lv[4];
            #pragma unroll
            for (int i = 0; i < 4; i++) sv[i] = Ss[nn][ty * 4 + i];
            #pragma unroll
            for (int j = 0; j < 4; j++) lv[j] = Ls[nn][tx * 4 + j];
            #pragma unroll
            for (int i = 0; i < 4; i++)
                #pragma unroll
                for (int j = 0; j < 4; j++)
                    acc[i][j] += sv[i] * lv[j];
        }
        __syncthreads();
    }

    float* Ab = A + (size_t)b * Cn * Cn;
    #pragma unroll
    for (int i = 0; i < 4; i++)
        #pragma unroll
        for (int j = 0; j < 4; j++)
            Ab[(size_t)(i0 + ty * 4 + i) * Cn + j0 + tx * 4 + j] = acc[i][j];
}

// ---------------------------------------------------------------------------
// row softmax (256) of gram + accumulate into att
// grid = B*C (2048), block 256
// ---------------------------------------------------------------------------
__global__ __launch_bounds__(256)
void softmax_rows_accum(const float* __restrict__ A, float* __restrict__ att, int init)
{
    __shared__ float red[256];
    const size_t base = (size_t)blockIdx.x * Cn;
    const int t = threadIdx.x;

    float v = A[base + t];
    red[t] = v; __syncthreads();
    for (int s = 128; s > 0; s >>= 1) {
        if (t < s) red[t] = fmaxf(red[t], red[t + s]);
        __syncthreads();
    }
    float m = red[0]; __syncthreads();
    float e = expf(v - m);
    red[t] = e; __syncthreads();
    for (int s = 128; s > 0; s >>= 1) {
        if (t < s) red[t] += red[t + s];
        __syncthreads();
    }
    float r = e / red[0];
    att[base + t] = init ? r : (att[base + t] + r);
}

// ---------------------------------------------------------------------------
// separable depthwise Gaussian, 'SAME' zero padding; one block per image
// grid = B*C (2048), block 256
// ---------------------------------------------------------------------------
struct G5 { float w[5]; };

__global__ __launch_bounds__(256)
void gauss_kernel(const float* __restrict__ in, float* __restrict__ out, G5 g, int r)
{
    __shared__ float s_in[64][65];
    __shared__ float s_h [64][65];

    const int img = blockIdx.x;
    const int t = threadIdx.x;
    const float* ip = in + (size_t)img * HWn;

    #pragma unroll
    for (int i = 0; i < 16; i++) {
        int px = t + i * 256;
        s_in[px >> 6][px & 63] = ip[px];
    }
    __syncthreads();
    #pragma unroll
    for (int i = 0; i < 16; i++) {
        int px = t + i * 256;
        int y = px >> 6, x = px & 63;
        float acc = 0.f;
        for (int d = -r; d <= r; d++) {
            int xx = x + d;
            if (xx >= 0 && xx < 64) acc += g.w[d + r] * s_in[y][xx];
        }
        s_h[y][x] = acc;
    }
    __syncthreads();
    float* op = out + (size_t)img * HWn;
    #pragma unroll
    for (int i = 0; i < 16; i++) {
        int px = t + i * 256;
        int y = px >> 6, x = px & 63;
        float acc = 0.f;
        for (int d = -r; d <= r; d++) {
            int yy = y + d;
            if (yy >= 0 && yy < 64) acc += g.w[d + r] * s_h[yy][x];
        }
        op[px] = acc;
    }
}

// ---------------------------------------------------------------------------
// attended[b,v,n] = sum_k ctx[b,k,v] * Q[b,k,n]
// grid (HW/64, C/64, B), block 256
// ---------------------------------------------------------------------------
__global__ __launch_bounds__(256)
void attended_kernel(const float* __restrict__ ctx, const float* __restrict__ Q,
                     float* __restrict__ out)
{
    __shared__ float Cs[16][64];
    __shared__ float Qs[16][64];

    const int b  = blockIdx.z;
    const int v0 = blockIdx.y * 64;
    const int n0 = blockIdx.x * 64;
    const int t  = threadIdx.x;
    const int tx = t & 15, ty = t >> 4;

    const float* cb = ctx + (size_t)b * Cn * Cn;
    const float* qb = Q   + (size_t)b * Cn * HWn;
    float acc[4][4] = {};

    for (int k0 = 0; k0 < Cn; k0 += 16) {
        #pragma unroll
        for (int r = 0; r < 4; r++) {
            int e = t + r * 256;
            int kk = e >> 6, uu = e & 63;
            Cs[kk][uu] = cb[(size_t)(k0 + kk) * Cn  + v0 + uu];
            Qs[kk][uu] = qb[(size_t)(k0 + kk) * HWn + n0 + uu];
        }
        __syncthreads();
        #pragma unroll
        for (int kk = 0; kk < 16; kk++) {
            float cv[4];
            #pragma unroll
            for (int i = 0; i < 4; i++) cv[i] = Cs[kk][ty * 4 + i];
            float4 qv = *(const float4*)&Qs[kk][tx * 4];
            float qs[4] = {qv.x, qv.y, qv.z, qv.w};
            #pragma unroll
            for (int i = 0; i < 4; i++)
                #pragma unroll
                for (int j = 0; j < 4; j++)
                    acc[i][j] += cv[i] * qs[j];
        }
        __syncthreads();
    }

    float* ob = out + (size_t)b * Cn * HWn;
    #pragma unroll
    for (int i = 0; i < 4; i++) {
        float4 o = {acc[i][0], acc[i][1], acc[i][2], acc[i][3]};
        *(float4*)&ob[(size_t)(v0 + ty * 4 + i) * HWn + n0 + tx * 4] = o;
    }
}

// ---------------------------------------------------------------------------
// fused epilogue:
//  out[b,k,n] = w0[k]*(sum_c Wr[k,c]*Atd[b,c,n] + br[k])
//             + w1[k]*(sum_c att[b,c,k]*Q[b,c,n])
// grid (HW/64, C/64, B), block 256
// ---------------------------------------------------------------------------
__global__ __launch_bounds__(256)
void final_kernel(const float* __restrict__ Atd, const float* __restrict__ Q,
                  const float* __restrict__ att, const float* __restrict__ Wr,
                  const float* __restrict__ br, const float* __restrict__ wdw,
                  float* __restrict__ out)
{
    __shared__ float Ws [16][65];  // Wr transposed: [c][k]
    __shared__ float ATs[16][64];  // att[c][k]
    __shared__ float As [16][64];  // Atd[c][n]
    __shared__ float Qs [16][64];  // Q[c][n]

    const int b  = blockIdx.z;
    const int k0 = blockIdx.y * 64;
    const int n0 = blockIdx.x * 64;
    const int t  = threadIdx.x;
    const int tx = t & 15, ty = t >> 4;

    const float* ab   = Atd + (size_t)b * Cn * HWn;
    const float* qb   = Q   + (size_t)b * Cn * HWn;
    const float* attb = att + (size_t)b * Cn * Cn;

    float acc1[4][4] = {};
    float acc2[4][4] = {};

    for (int c0 = 0; c0 < Cn; c0 += 16) {
        #pragma unroll
        for (int r = 0; r < 4; r++) {
            int e = t + r * 256;
            int kk = e >> 4, cc = e & 15;
            Ws[cc][kk] = Wr[(size_t)(k0 + kk) * Cn + c0 + cc];
        }
        #pragma unroll
        for (int r = 0; r < 4; r++) {
            int e = t + r * 256;
            int cc = e >> 6, uu = e & 63;
            ATs[cc][uu] = attb[(size_t)(c0 + cc) * Cn  + k0 + uu];
            As [cc][uu] = ab  [(size_t)(c0 + cc) * HWn + n0 + uu];
            Qs [cc][uu] = qb  [(size_t)(c0 + cc) * HWn + n0 + uu];
        }
        __syncthreads();
        #pragma unroll
        for (int cc = 0; cc < 16; cc++) {
            float w[4], a[4];
            #pragma unroll
            for (int i = 0; i < 4; i++) {
                w[i] = Ws [cc][ty * 4 + i];
                a[i] = ATs[cc][ty * 4 + i];
            }
            float4 av = *(const float4*)&As[cc][tx * 4];
            float4 qv = *(const float4*)&Qs[cc][tx * 4];
            float as[4] = {av.x, av.y, av.z, av.w};
            float qs[4] = {qv.x, qv.y, qv.z, qv.w};
            #pragma unroll
            for (int i = 0; i < 4; i++)
                #pragma unroll
                for (int j = 0; j < 4; j++) {
                    acc1[i][j] += w[i] * as[j];
                    acc2[i][j] += a[i] * qs[j];
                }
        }
        __syncthreads();
    }

    float* ob = out + (size_t)b * Cn * HWn;
    #pragma unroll
    for (int i = 0; i < 4; i++) {
        int k = k0 + ty * 4 + i;
        float w0 = wdw[2 * k], w1 = wdw[2 * k + 1];
        float bb = br[k];
        float4 o;
        o.x = w0 * (acc1[i][0] + bb) + w1 * acc2[i][0];
        o.y = w0 * (acc1[i][1] + bb) + w1 * acc2[i][1];
        o.z = w0 * (acc1[i][2] + bb) + w1 * acc2[i][2];
        o.w = w0 * (acc1[i][3] + bb) + w1 * acc2[i][3];
        *(float4*)&ob[(size_t)k * HWn + n0 + tx * 4] = o;
    }
}

// ---------------------------------------------------------------------------
// host
// ---------------------------------------------------------------------------
static void make_gauss1d(int ksize, double sigma, float* w)
{
    double g[5], s = 0.0;
    for (int i = 0; i < ksize; i++) {
        double d = (double)i - (ksize - 1) / 2.0;
        g[i] = exp(-(d * d) / (2.0 * sigma * sigma));
        s += g[i];
    }
    for (int i = 0; i < ksize; i++) w[i] = (float)(g[i] / s);
}

extern "C" void kernel_launch(void* const* d_in, const int* in_sizes, int n_in,
                              void* d_out, int out_size)
{
    (void)in_sizes; (void)n_in; (void)out_size;
    const float* x   = (const float*)d_in[0];
    const float* Wk  = (const float*)d_in[1];
    const float* bk  = (const float*)d_in[2];
    const float* Wq  = (const float*)d_in[3];
    const float* bq  = (const float*)d_in[4];
    const float* Wv  = (const float*)d_in[5];
    const float* bv  = (const float*)d_in[6];
    const float* Wr  = (const float*)d_in[7];
    const float* br  = (const float*)d_in[8];
    const float* wdw = (const float*)d_in[9];
    float* out = (float*)d_out;

    float *gK, *gQ, *gV, *gG1, *gG2, *gS, *gAtd, *gCtx, *gGram, *gAttm;
    cudaGetSymbolAddress((void**)&gK,    g_K);
    cudaGetSymbolAddress((void**)&gQ,    g_Q);
    cudaGetSymbolAddress((void**)&gV,    g_V);
    cudaGetSymbolAddress((void**)&gG1,   g_G1);
    cudaGetSymbolAddress((void**)&gG2,   g_G2);
    cudaGetSymbolAddress((void**)&gS,    g_S);
    cudaGetSymbolAddress((void**)&gAtd,  g_Atd);
    cudaGetSymbolAddress((void**)&gCtx,  g_Ctx);
    cudaGetSymbolAddress((void**)&gGram, g_Gram);
    cudaGetSymbolAddress((void**)&gAttm, g_Attm);

    // Gaussian kernels (match cv2.getGaussianKernel in double precision)
    const double SIGMA = 1.6;
    const double S_VAL = cbrt(2.0);
    G5 g3 = {}, g5 = {};
    make_gauss1d(3, SIGMA, g3.w);
    make_gauss1d(5, SIGMA * S_VAL, g5.w);

    dim3 gGemm(HWn / 64, Cn / 64, Bn);   // (64, 4, 8)
    dim3 gGram4(4, 4, Bn);

    // 1x1 convs -> K, Q, V
    conv1x1_kernel<<<gGemm, 256>>>(x, Wk, bk, gK);
    conv1x1_kernel<<<gGemm, 256>>>(x, Wq, bq, gQ);
    conv1x1_kernel<<<gGemm, 256>>>(x, Wv, bv, gV);

    // softmaxes
    softmax_hw_kernel<<<Bn * Cn, 256>>>(gK, gK, gK, 0);   // keys: softmax over HW (in place)
    softmax_c_kernel<<<Bn * HWn / 256, 256>>>(gQ);        // queries: softmax over C

    // Gaussian pyramid
    gauss_kernel<<<Bn * Cn, 256>>>(x,   gG1, g3, 1);
    gauss_kernel<<<Bn * Cn, 256>>>(gG1, gG2, g5, 2);

    // efficient attention: context + attended
    gram_kernel<<<gGram4, 256>>>(gK, gV, gV, gCtx, 0);
    attended_kernel<<<gGemm, 256>>>(gCtx, gQ, gAtd);

    // channel attention: level 0 (x), level 1 (x-G1), level 2 (G1-G2)
    softmax_hw_kernel<<<Bn * Cn, 256>>>(x, x, gS, 0);
    gram_kernel<<<gGram4, 256>>>(gS, x, x, gGram, 0);
    softmax_rows_accum<<<Bn * Cn, 256>>>(gGram, gAttm, 1);

    softmax_hw_kernel<<<Bn * Cn, 256>>>(x, gG1, gS, 1);
    gram_kernel<<<gGram4, 256>>>(gS, x, gG1, gGram, 1);
    softmax_rows_accum<<<Bn * Cn, 256>>>(gGram, gAttm, 0);

    softmax_hw_kernel<<<Bn * Cn, 256>>>(gG1, gG2, gS, 1);
    gram_kernel<<<gGram4, 256>>>(gS, gG1, gG2, gGram, 1);
    softmax_rows_accum<<<Bn * Cn, 256>>>(gGram, gAttm, 0);

    // fused: eff = Wr@attended + br ; freq = att^T @ Q ; out = w0*eff + w1*freq
    final_kernel<<<gGemm, 256>>>(gAtd, gQ, gAttm, Wr, br, wdw, out);
}

// round 4
// speedup vs baseline: 4.0342x; 4.0342x over previous
#include <cuda_runtime.h>
#include <math.h>
#include <stdint.h>

// ---------------------------------------------------------------------------
// EfficientFrequencyAttention  B=8, C=256, H=W=64   — tf32 tensor-core version
// ---------------------------------------------------------------------------
#define Bn  8
#define Cn  256
#define Hn  64
#define Wn  64
#define HWn 4096
#define BCHW (Bn*Cn*HWn)   // 8,388,608
#define BCC  (Bn*Cn*Cn)    // 524,288
#define SPLITK 8

// ----------------------------- scratch (static, no allocation) -------------
__device__ float g_K   [BCHW];
__device__ float g_Q   [BCHW];
__device__ float g_V   [BCHW];
__device__ float g_G1  [BCHW];
__device__ float g_G2  [BCHW];
__device__ float g_S   [BCHW];   // per-level softmax
__device__ float g_D   [BCHW];   // per-level raw Laplacian diff
__device__ float g_Atd [BCHW];   // attended
__device__ float g_Ctx [BCC];
__device__ float g_Attm[BCC];    // accumulated channel attention
__device__ float g_Part[BCC * SPLITK];  // split-K gram partials

// ----------------------------- mma / cp.async helpers ----------------------
__device__ __forceinline__ unsigned f2tf(float f) {
    unsigned u;
    asm("cvt.rna.tf32.f32 %0, %1;" : "=r"(u) : "f"(f));
    return u;
}

__device__ __forceinline__ void mma8(float* c, const unsigned* a, const unsigned* b) {
    asm volatile(
        "mma.sync.aligned.m16n8k8.row.col.f32.tf32.tf32.f32 "
        "{%0,%1,%2,%3},{%4,%5,%6,%7},{%8,%9},{%0,%1,%2,%3};\n"
        : "+f"(c[0]), "+f"(c[1]), "+f"(c[2]), "+f"(c[3])
        : "r"(a[0]), "r"(a[1]), "r"(a[2]), "r"(a[3]),
          "r"(b[0]), "r"(b[1]));
}

__device__ __forceinline__ void cp16(uint32_t dst, const void* src) {
    asm volatile("cp.async.ca.shared.global [%0], [%1], 16;" :: "r"(dst), "l"(src));
}
#define CP_COMMIT() asm volatile("cp.async.commit_group;")
#define CP_WAIT1()  asm volatile("cp.async.wait_group 1;")
#define CP_WAIT0()  asm volatile("cp.async.wait_group 0;")

// smem tile strides (floats). Padding chosen for conflict-free fragment LDS.
#define A_STR 4608    // 128 x 36  (A row-major [m][k])
#define B_STR 2304    // 32  x 72  (B [k][n])
#define L_STR 2304    // 64  x 36  (L [n][k])
#define T_STR 4352    // 32  x 136 (A-transposed source [k][m])

// ---------------------------------------------------------------------------
// conv1x1 (tensor):  Y[b,m,n] = sum_k W[m,k] * X[b,k,n] + bias[m]
// block 256 thr, tile 128(M) x 64(N), K-chunk 32, double-buffered cp.async
// grid (64, 2, 8)
// ---------------------------------------------------------------------------
__global__ __launch_bounds__(256)
void conv_tc(const float* __restrict__ X, const float* __restrict__ Wm,
             const float* __restrict__ bias, float* __restrict__ Y)
{
    extern __shared__ float sm[];
    float* As = sm;              // [2][128][36]
    float* Bs = sm + 2 * A_STR;  // [2][32][72]
    uint32_t sb = (uint32_t)__cvta_generic_to_shared(sm);

    const int b  = blockIdx.z;
    const int m0 = blockIdx.y * 128;
    const int n0 = blockIdx.x * 64;
    const int t  = threadIdx.x;
    const float* Xb = X + (size_t)b * Cn * HWn;

    const int lane = t & 31, warp = t >> 5;
    const int wm = (warp >> 1) * 32, wn = (warp & 1) * 32;
    const int g = lane >> 2, t4 = lane & 3;

    float acc[2][4][4] = {};

    auto issue = [&](int c, int st) {
        const int kc = c * 32;
        #pragma unroll
        for (int i = 0; i < 4; i++) {           // A: 128x32
            int row = (t >> 3) + i * 32, col = (t & 7) * 4;
            cp16(sb + (uint32_t)(st * A_STR + row * 36 + col) * 4,
                 Wm + (size_t)(m0 + row) * Cn + kc + col);
        }
        #pragma unroll
        for (int i = 0; i < 2; i++) {           // B: 32x64
            int row = (t >> 4) + i * 16, col = (t & 15) * 4;
            cp16(sb + (uint32_t)(2 * A_STR + st * B_STR + row * 72 + col) * 4,
                 Xb + (size_t)(kc + row) * HWn + n0 + col);
        }
        CP_COMMIT();
    };

    issue(0, 0);
    const int NC = Cn / 32;  // 8
    for (int c = 0; c < NC; c++) {
        int st = c & 1;
        if (c + 1 < NC) { issue(c + 1, st ^ 1); CP_WAIT1(); }
        else            { CP_WAIT0(); }
        __syncthreads();
        const float* A = As + st * A_STR;
        const float* B = Bs + st * B_STR;
        #pragma unroll
        for (int ks = 0; ks < 4; ks++) {
            const int k8 = ks * 8;
            unsigned af[2][4], bf[4][2];
            #pragma unroll
            for (int mi = 0; mi < 2; mi++) {
                int r = wm + mi * 16 + g;
                af[mi][0] = f2tf(A[r * 36 + k8 + t4]);
                af[mi][1] = f2tf(A[(r + 8) * 36 + k8 + t4]);
                af[mi][2] = f2tf(A[r * 36 + k8 + t4 + 4]);
                af[mi][3] = f2tf(A[(r + 8) * 36 + k8 + t4 + 4]);
            }
            #pragma unroll
            for (int ni = 0; ni < 4; ni++) {
                int nb = wn + ni * 8 + g;
                bf[ni][0] = f2tf(B[(k8 + t4) * 72 + nb]);
                bf[ni][1] = f2tf(B[(k8 + t4 + 4) * 72 + nb]);
            }
            #pragma unroll
            for (int mi = 0; mi < 2; mi++)
                #pragma unroll
                for (int ni = 0; ni < 4; ni++)
                    mma8(acc[mi][ni], af[mi], bf[ni]);
        }
        __syncthreads();
    }

    float* Yb = Y + (size_t)b * Cn * HWn;
    #pragma unroll
    for (int mi = 0; mi < 2; mi++) {
        int r0 = m0 + wm + mi * 16 + g, r1 = r0 + 8;
        float bv0 = bias[r0], bv1 = bias[r1];
        #pragma unroll
        for (int ni = 0; ni < 4; ni++) {
            int col = n0 + wn + ni * 8 + 2 * t4;
            float2 v0 = {acc[mi][ni][0] + bv0, acc[mi][ni][1] + bv0};
            float2 v1 = {acc[mi][ni][2] + bv1, acc[mi][ni][3] + bv1};
            *(float2*)&Yb[(size_t)r0 * HWn + col] = v0;
            *(float2*)&Yb[(size_t)r1 * HWn + col] = v1;
        }
    }
}

// ---------------------------------------------------------------------------
// gram (tensor, split-K):  part[z,m,n] = sum_{k in split} S[b,m,k] * L[b,n,k]
// z = b*8+s ; K-range per block = 512. grid (4, 2, 64)
// ---------------------------------------------------------------------------
__global__ __launch_bounds__(256)
void gram_tc(const float* __restrict__ S, const float* __restrict__ L,
             float* __restrict__ part)
{
    extern __shared__ float sm[];
    float* As = sm;              // [2][128][36]  (S tile, [m][k])
    float* Ls = sm + 2 * A_STR;  // [2][64][36]   (L tile, [n][k])
    uint32_t sb = (uint32_t)__cvta_generic_to_shared(sm);

    const int z = blockIdx.z, b = z >> 3, s = z & 7;
    const int m0 = blockIdx.y * 128;
    const int n0 = blockIdx.x * 64;
    const int kb = s * (HWn / SPLITK);          // 512
    const int t = threadIdx.x;
    const float* Sb = S + (size_t)b * Cn * HWn;
    const float* Lb = L + (size_t)b * Cn * HWn;

    const int lane = t & 31, warp = t >> 5;
    const int wm = (warp >> 1) * 32, wn = (warp & 1) * 32;
    const int g = lane >> 2, t4 = lane & 3;

    float acc[2][4][4] = {};

    auto issue = [&](int c, int st) {
        const int kc = kb + c * 32;
        #pragma unroll
        for (int i = 0; i < 4; i++) {           // S: 128x32
            int row = (t >> 3) + i * 32, col = (t & 7) * 4;
            cp16(sb + (uint32_t)(st * A_STR + row * 36 + col) * 4,
                 Sb + (size_t)(m0 + row) * HWn + kc + col);
        }
        #pragma unroll
        for (int i = 0; i < 2; i++) {           // L: 64x32
            int row = (t >> 3) + i * 32, col = (t & 7) * 4;
            cp16(sb + (uint32_t)(2 * A_STR + st * L_STR + row * 36 + col) * 4,
                 Lb + (size_t)(n0 + row) * HWn + kc + col);
        }
        CP_COMMIT();
    };

    issue(0, 0);
    const int NC = (HWn / SPLITK) / 32;  // 16
    for (int c = 0; c < NC; c++) {
        int st = c & 1;
        if (c + 1 < NC) { issue(c + 1, st ^ 1); CP_WAIT1(); }
        else            { CP_WAIT0(); }
        __syncthreads();
        const float* A  = As + st * A_STR;
        const float* Lt = Ls + st * L_STR;
        #pragma unroll
        for (int ks = 0; ks < 4; ks++) {
            const int k8 = ks * 8;
            unsigned af[2][4], bf[4][2];
            #pragma unroll
            for (int mi = 0; mi < 2; mi++) {
                int r = wm + mi * 16 + g;
                af[mi][0] = f2tf(A[r * 36 + k8 + t4]);
                af[mi][1] = f2tf(A[(r + 8) * 36 + k8 + t4]);
                af[mi][2] = f2tf(A[r * 36 + k8 + t4 + 4]);
                af[mi][3] = f2tf(A[(r + 8) * 36 + k8 + t4 + 4]);
            }
            #pragma unroll
            for (int ni = 0; ni < 4; ni++) {
                int nb = wn + ni * 8 + g;
                bf[ni][0] = f2tf(Lt[nb * 36 + k8 + t4]);
                bf[ni][1] = f2tf(Lt[nb * 36 + k8 + t4 + 4]);
            }
            #pragma unroll
            for (int mi = 0; mi < 2; mi++)
                #pragma unroll
                for (int ni = 0; ni < 4; ni++)
                    mma8(acc[mi][ni], af[mi], bf[ni]);
        }
        __syncthreads();
    }

    float* P = part + (size_t)z * Cn * Cn;
    #pragma unroll
    for (int mi = 0; mi < 2; mi++) {
        int r0 = m0 + wm + mi * 16 + g, r1 = r0 + 8;
        #pragma unroll
        for (int ni = 0; ni < 4; ni++) {
            int col = n0 + wn + ni * 8 + 2 * t4;
            *(float2*)&P[(size_t)r0 * Cn + col] = make_float2(acc[mi][ni][0], acc[mi][ni][1]);
            *(float2*)&P[(size_t)r1 * Cn + col] = make_float2(acc[mi][ni][2], acc[mi][ni][3]);
        }
    }
}

// ---------------------------------------------------------------------------
// attended (tensor): out[b,m,n] = sum_k ctx[b,k,m] * Q[b,k,n]   grid (64,2,8)
// ---------------------------------------------------------------------------
__global__ __launch_bounds__(256)
void attended_tc(const float* __restrict__ ctx, const float* __restrict__ Q,
                 float* __restrict__ out)
{
    extern __shared__ float sm[];
    float* Cs = sm;              // [2][32][136]  (ctx tile, [k][m])
    float* Bs = sm + 2 * T_STR;  // [2][32][72]   (Q tile,   [k][n])
    uint32_t sb = (uint32_t)__cvta_generic_to_shared(sm);

    const int b  = blockIdx.z;
    const int m0 = blockIdx.y * 128;
    const int n0 = blockIdx.x * 64;
    const int t  = threadIdx.x;
    const float* cb = ctx + (size_t)b * Cn * Cn;
    const float* qb = Q   + (size_t)b * Cn * HWn;

    const int lane = t & 31, warp = t >> 5;
    const int wm = (warp >> 1) * 32, wn = (warp & 1) * 32;
    const int g = lane >> 2, t4 = lane & 3;

    float acc[2][4][4] = {};

    auto issue = [&](int c, int st) {
        const int kc = c * 32;
        #pragma unroll
        for (int i = 0; i < 4; i++) {           // ctx: 32(k)x128(m)
            int row = (t >> 5) + i * 8, col = (t & 31) * 4;
            cp16(sb + (uint32_t)(st * T_STR + row * 136 + col) * 4,
                 cb + (size_t)(kc + row) * Cn + m0 + col);
        }
        #pragma unroll
        for (int i = 0; i < 2; i++) {           // Q: 32x64
            int row = (t >> 4) + i * 16, col = (t & 15) * 4;
            cp16(sb + (uint32_t)(2 * T_STR + st * B_STR + row * 72 + col) * 4,
                 qb + (size_t)(kc + row) * HWn + n0 + col);
        }
        CP_COMMIT();
    };

    issue(0, 0);
    const int NC = Cn / 32;  // 8
    for (int c = 0; c < NC; c++) {
        int st = c & 1;
        if (c + 1 < NC) { issue(c + 1, st ^ 1); CP_WAIT1(); }
        else            { CP_WAIT0(); }
        __syncthreads();
        const float* A = Cs + st * T_STR;
        const float* B = Bs + st * B_STR;
        #pragma unroll
        for (int ks = 0; ks < 4; ks++) {
            const int k8 = ks * 8;
            unsigned af[2][4], bf[4][2];
            #pragma unroll
            for (int mi = 0; mi < 2; mi++) {
                int r = wm + mi * 16 + g;
                af[mi][0] = f2tf(A[(k8 + t4) * 136 + r]);
                af[mi][1] = f2tf(A[(k8 + t4) * 136 + r + 8]);
                af[mi][2] = f2tf(A[(k8 + t4 + 4) * 136 + r]);
                af[mi][3] = f2tf(A[(k8 + t4 + 4) * 136 + r + 8]);
            }
            #pragma unroll
            for (int ni = 0; ni < 4; ni++) {
                int nb = wn + ni * 8 + g;
                bf[ni][0] = f2tf(B[(k8 + t4) * 72 + nb]);
                bf[ni][1] = f2tf(B[(k8 + t4 + 4) * 72 + nb]);
            }
            #pragma unroll
            for (int mi = 0; mi < 2; mi++)
                #pragma unroll
                for (int ni = 0; ni < 4; ni++)
                    mma8(acc[mi][ni], af[mi], bf[ni]);
        }
        __syncthreads();
    }

    float* ob = out + (size_t)b * Cn * HWn;
    #pragma unroll
    for (int mi = 0; mi < 2; mi++) {
        int r0 = m0 + wm + mi * 16 + g, r1 = r0 + 8;
        #pragma unroll
        for (int ni = 0; ni < 4; ni++) {
            int col = n0 + wn + ni * 8 + 2 * t4;
            *(float2*)&ob[(size_t)r0 * HWn + col] = make_float2(acc[mi][ni][0], acc[mi][ni][1]);
            *(float2*)&ob[(size_t)r1 * HWn + col] = make_float2(acc[mi][ni][2], acc[mi][ni][3]);
        }
    }
}

// ---------------------------------------------------------------------------
// fused final (tensor):
//  out[b,m,n] = w0[m]*(sum_k Wr[m,k]*Atd[b,k,n] + br[m])
//             + w1[m]*(sum_k att[b,k,m]*Q[b,k,n])
// single-buffered (4 tiles, 54KB).  grid (64,2,8)
// ---------------------------------------------------------------------------
__global__ __launch_bounds__(256)
void final_tc(const float* __restrict__ Atd, const float* __restrict__ Q,
              const float* __restrict__ att, const float* __restrict__ Wr,
              const float* __restrict__ br, const float* __restrict__ wdw,
              float* __restrict__ out)
{
    extern __shared__ float sm[];
    float* As  = sm;                                // [128][36]  Wr
    float* Ts  = sm + A_STR;                        // [32][136]  att (k,m)
    float* B1s = sm + A_STR + T_STR;                // [32][72]   Atd
    float* B2s = sm + A_STR + T_STR + B_STR;        // [32][72]   Q
    uint32_t sb = (uint32_t)__cvta_generic_to_shared(sm);

    const int b  = blockIdx.z;
    const int m0 = blockIdx.y * 128;
    const int n0 = blockIdx.x * 64;
    const int t  = threadIdx.x;
    const float* ab   = Atd + (size_t)b * Cn * HWn;
    const float* qb   = Q   + (size_t)b * Cn * HWn;
    const float* attb = att + (size_t)b * Cn * Cn;

    const int lane = t & 31, warp = t >> 5;
    const int wm = (warp >> 1) * 32, wn = (warp & 1) * 32;
    const int g = lane >> 2, t4 = lane & 3;

    float acc1[2][4][4] = {};
    float acc2[2][4][4] = {};

    const int NC = Cn / 32;  // 8
    for (int c = 0; c < NC; c++) {
        const int kc = c * 32;
        if (c > 0) __syncthreads();   // previous compute done before overwrite
        #pragma unroll
        for (int i = 0; i < 4; i++) { // Wr: 128x32
            int row = (t >> 3) + i * 32, col = (t & 7) * 4;
            cp16(sb + (uint32_t)(row * 36 + col) * 4,
                 Wr + (size_t)(m0 + row) * Cn + kc + col);
        }
        #pragma unroll
        for (int i = 0; i < 4; i++) { // att: 32(k)x128(m)
            int row = (t >> 5) + i * 8, col = (t & 31) * 4;
            cp16(sb + (uint32_t)(A_STR + row * 136 + col) * 4,
                 attb + (size_t)(kc + row) * Cn + m0 + col);
        }
        #pragma unroll
        for (int i = 0; i < 2; i++) { // Atd & Q: 32x64
            int row = (t >> 4) + i * 16, col = (t & 15) * 4;
            cp16(sb + (uint32_t)(A_STR + T_STR + row * 72 + col) * 4,
                 ab + (size_t)(kc + row) * HWn + n0 + col);
            cp16(sb + (uint32_t)(A_STR + T_STR + B_STR + row * 72 + col) * 4,
                 qb + (size_t)(kc + row) * HWn + n0 + col);
        }
        CP_COMMIT();
        CP_WAIT0();
        __syncthreads();

        #pragma unroll
        for (int ks = 0; ks < 4; ks++) {
            const int k8 = ks * 8;
            unsigned a1f[2][4], a2f[2][4], b1f[4][2], b2f[4][2];
            #pragma unroll
            for (int mi = 0; mi < 2; mi++) {
                int r = wm + mi * 16 + g;
                a1f[mi][0] = f2tf(As[r * 36 + k8 + t4]);
                a1f[mi][1] = f2tf(As[(r + 8) * 36 + k8 + t4]);
                a1f[mi][2] = f2tf(As[r * 36 + k8 + t4 + 4]);
                a1f[mi][3] = f2tf(As[(r + 8) * 36 + k8 + t4 + 4]);
                a2f[mi][0] = f2tf(Ts[(k8 + t4) * 136 + r]);
                a2f[mi][1] = f2tf(Ts[(k8 + t4) * 136 + r + 8]);
                a2f[mi][2] = f2tf(Ts[(k8 + t4 + 4) * 136 + r]);
                a2f[mi][3] = f2tf(Ts[(k8 + t4 + 4) * 136 + r + 8]);
            }
            #pragma unroll
            for (int ni = 0; ni < 4; ni++) {
                int nb = wn + ni * 8 + g;
                b1f[ni][0] = f2tf(B1s[(k8 + t4) * 72 + nb]);
                b1f[ni][1] = f2tf(B1s[(k8 + t4 + 4) * 72 + nb]);
                b2f[ni][0] = f2tf(B2s[(k8 + t4) * 72 + nb]);
                b2f[ni][1] = f2tf(B2s[(k8 + t4 + 4) * 72 + nb]);
            }
            #pragma unroll
            for (int mi = 0; mi < 2; mi++)
                #pragma unroll
                for (int ni = 0; ni < 4; ni++) {
                    mma8(acc1[mi][ni], a1f[mi], b1f[ni]);
                    mma8(acc2[mi][ni], a2f[mi], b2f[ni]);
                }
        }
    }

    float* ob = out + (size_t)b * Cn * HWn;
    #pragma unroll
    for (int mi = 0; mi < 2; mi++) {
        int r0 = m0 + wm + mi * 16 + g, r1 = r0 + 8;
        float w00 = wdw[2 * r0], w01 = wdw[2 * r0 + 1], bb0 = br[r0];
        float w10 = wdw[2 * r1], w11 = wdw[2 * r1 + 1], bb1 = br[r1];
        #pragma unroll
        for (int ni = 0; ni < 4; ni++) {
            int col = n0 + wn + ni * 8 + 2 * t4;
            float2 v0, v1;
            v0.x = w00 * (acc1[mi][ni][0] + bb0) + w01 * acc2[mi][ni][0];
            v0.y = w00 * (acc1[mi][ni][1] + bb0) + w01 * acc2[mi][ni][1];
            v1.x = w10 * (acc1[mi][ni][2] + bb1) + w11 * acc2[mi][ni][2];
            v1.y = w10 * (acc1[mi][ni][3] + bb1) + w11 * acc2[mi][ni][3];
            *(float2*)&ob[(size_t)r0 * HWn + col] = v0;
            *(float2*)&ob[(size_t)r1 * HWn + col] = v1;
        }
    }
}

// ---------------------------------------------------------------------------
// softmax over HW per (b,c) row; optionally over (A - Bm); optionally writes
// the raw (pre-softmax) value to 'raw'.  grid B*C, block 256
// ---------------------------------------------------------------------------
__global__ __launch_bounds__(256)
void softmax_hw_kernel(const float* __restrict__ A, const float* __restrict__ Bm,
                       float* __restrict__ out, float* __restrict__ raw, int hasB)
{
    __shared__ float red[256];
    const size_t base = (size_t)blockIdx.x * HWn;
    const int t = threadIdx.x;

    float v[16];
    float m = -INFINITY;
    #pragma unroll
    for (int i = 0; i < 16; i++) {
        size_t idx = base + t + i * 256;
        float a = A[idx];
        if (hasB) a -= Bm[idx];
        if (raw) raw[idx] = a;
        v[i] = a;
        m = fmaxf(m, a);
    }
    red[t] = m; __syncthreads();
    for (int s = 128; s > 0; s >>= 1) {
        if (t < s) red[t] = fmaxf(red[t], red[t + s]);
        __syncthreads();
    }
    m = red[0]; __syncthreads();

    float sum = 0.f;
    #pragma unroll
    for (int i = 0; i < 16; i++) { v[i] = expf(v[i] - m); sum += v[i]; }
    red[t] = sum; __syncthreads();
    for (int s = 128; s > 0; s >>= 1) {
        if (t < s) red[t] += red[t + s];
        __syncthreads();
    }
    float inv = 1.0f / red[0];
    #pragma unroll
    for (int i = 0; i < 16; i++) out[base + t + i * 256] = v[i] * inv;
}

// ---------------------------------------------------------------------------
// softmax over channel axis (256), smem-cached: one block per (b, 64 columns)
// grid = B*64 = 512, block 256, dyn smem 256*65+512 floats
// ---------------------------------------------------------------------------
__global__ __launch_bounds__(256)
void softmax_c_smem(float* __restrict__ Q)
{
    extern __shared__ float sm[];
    const int P = 65;
    float* red = sm + 256 * P;
    const int blk = blockIdx.x;
    const int b = blk >> 6, n0 = (blk & 63) * 64;
    float* base = Q + (size_t)b * Cn * HWn + n0;
    const int t = threadIdx.x, nl = t & 63, cs = t >> 6;

    #pragma unroll 4
    for (int i = 0; i < 64; i++) {
        int c = cs * 64 + i;
        sm[c * P + nl] = base[(size_t)c * HWn + nl];
    }
    __syncthreads();
    float m = -INFINITY;
    #pragma unroll 4
    for (int i = 0; i < 64; i++) m = fmaxf(m, sm[(cs * 64 + i) * P + nl]);
    red[cs * 64 + nl] = m;
    __syncthreads();
    if (t < 64)
        red[t] = fmaxf(fmaxf(red[t], red[64 + t]), fmaxf(red[128 + t], red[192 + t]));
    __syncthreads();
    m = red[nl];
    __syncthreads();
    float s = 0.f;
    #pragma unroll 4
    for (int i = 0; i < 64; i++) {
        int c = cs * 64 + i;
        float e = expf(sm[c * P + nl] - m);
        sm[c * P + nl] = e;
        s += e;
    }
    red[cs * 64 + nl] = s;
    __syncthreads();
    if (t < 64) red[t] = red[t] + red[64 + t] + red[128 + t] + red[192 + t];
    __syncthreads();
    float inv = 1.0f / red[nl];
    #pragma unroll 4
    for (int i = 0; i < 64; i++) {
        int c = cs * 64 + i;
        base[(size_t)c * HWn + nl] = sm[c * P + nl] * inv;
    }
}

// ---------------------------------------------------------------------------
// ctx reduce: ctx[b][r] = sum_s part[b*8+s][r].  grid 2048, block 256
// ---------------------------------------------------------------------------
__global__ __launch_bounds__(256)
void reduce_ctx_kernel(const float* __restrict__ part, float* __restrict__ ctx)
{
    const int e = blockIdx.x * 256 + threadIdx.x;   // 0 .. BCC-1
    const int b = e >> 16, r = e & 65535;
    float v = 0.f;
    #pragma unroll
    for (int s = 0; s < SPLITK; s++)
        v += part[((size_t)(b * SPLITK + s) << 16) + r];
    ctx[e] = v;
}

// ---------------------------------------------------------------------------
// row softmax (256) of split-K gram partials, accumulate into att
// grid = B*C, block 256
// ---------------------------------------------------------------------------
__global__ __launch_bounds__(256)
void softmax_rows_accum(const float* __restrict__ part, float* __restrict__ att, int init)
{
    __shared__ float red[256];
    const int row = blockIdx.x;
    const int b = row >> 8, i = row & 255;
    const int t = threadIdx.x;

    float v = 0.f;
    size_t base = ((size_t)b * SPLITK << 16) + (size_t)i * Cn + t;
    #pragma unroll
    for (int s = 0; s < SPLITK; s++) v += part[base + ((size_t)s << 16)];

    red[t] = v; __syncthreads();
    for (int s = 128; s > 0; s >>= 1) {
        if (t < s) red[t] = fmaxf(red[t], red[t + s]);
        __syncthreads();
    }
    float m = red[0]; __syncthreads();
    float e = expf(v - m);
    red[t] = e; __syncthreads();
    for (int s = 128; s > 0; s >>= 1) {
        if (t < s) red[t] += red[t + s];
        __syncthreads();
    }
    float r = e / red[0];
    size_t o = (size_t)row * Cn + t;
    att[o] = init ? r : (att[o] + r);
}

// ---------------------------------------------------------------------------
// separable depthwise Gaussian, 'SAME' zero padding; one block per image
// ---------------------------------------------------------------------------
struct G5 { float w[5]; };

__global__ __launch_bounds__(256)
void gauss_kernel(const float* __restrict__ in, float* __restrict__ out, G5 g, int r)
{
    __shared__ float s_in[64][65];
    __shared__ float s_h [64][65];

    const int img = blockIdx.x;
    const int t = threadIdx.x;
    const float* ip = in + (size_t)img * HWn;

    #pragma unroll
    for (int i = 0; i < 16; i++) {
        int px = t + i * 256;
        s_in[px >> 6][px & 63] = ip[px];
    }
    __syncthreads();
    #pragma unroll
    for (int i = 0; i < 16; i++) {
        int px = t + i * 256;
        int y = px >> 6, x = px & 63;
        float acc = 0.f;
        for (int d = -r; d <= r; d++) {
            int xx = x + d;
            if (xx >= 0 && xx < 64) acc += g.w[d + r] * s_in[y][xx];
        }
        s_h[y][x] = acc;
    }
    __syncthreads();
    float* op = out + (size_t)img * HWn;
    #pragma unroll
    for (int i = 0; i < 16; i++) {
        int px = t + i * 256;
        int y = px >> 6, x = px & 63;
        float acc = 0.f;
        for (int d = -r; d <= r; d++) {
            int yy = y + d;
            if (yy >= 0 && yy < 64) acc += g.w[d + r] * s_h[yy][x];
        }
        op[px] = acc;
    }
}

// ---------------------------------------------------------------------------
// host
// ---------------------------------------------------------------------------
static void make_gauss1d(int ksize, double sigma, float* w)
{
    double g[5], s = 0.0;
    for (int i = 0; i < ksize; i++) {
        double d = (double)i - (ksize - 1) / 2.0;
        g[i] = exp(-(d * d) / (2.0 * sigma * sigma));
        s += g[i];
    }
    for (int i = 0; i < ksize; i++) w[i] = (float)(g[i] / s);
}

extern "C" void kernel_launch(void* const* d_in, const int* in_sizes, int n_in,
                              void* d_out, int out_size)
{
    (void)in_sizes; (void)n_in; (void)out_size;
    const float* x   = (const float*)d_in[0];
    const float* Wk  = (const float*)d_in[1];
    const float* bk  = (const float*)d_in[2];
    const float* Wq  = (const float*)d_in[3];
    const float* bq  = (const float*)d_in[4];
    const float* Wv  = (const float*)d_in[5];
    const float* bv  = (const float*)d_in[6];
    const float* Wr  = (const float*)d_in[7];
    const float* br  = (const float*)d_in[8];
    const float* wdw = (const float*)d_in[9];
    float* out = (float*)d_out;

    float *gK, *gQ, *gV, *gG1, *gG2, *gS, *gD, *gAtd, *gCtx, *gAttm, *gPart;
    cudaGetSymbolAddress((void**)&gK,    g_K);
    cudaGetSymbolAddress((void**)&gQ,    g_Q);
    cudaGetSymbolAddress((void**)&gV,    g_V);
    cudaGetSymbolAddress((void**)&gG1,   g_G1);
    cudaGetSymbolAddress((void**)&gG2,   g_G2);
    cudaGetSymbolAddress((void**)&gS,    g_S);
    cudaGetSymbolAddress((void**)&gD,    g_D);
    cudaGetSymbolAddress((void**)&gAtd,  g_Atd);
    cudaGetSymbolAddress((void**)&gCtx,  g_Ctx);
    cudaGetSymbolAddress((void**)&gAttm, g_Attm);
    cudaGetSymbolAddress((void**)&gPart, g_Part);

    // dynamic smem opt-in (>48KB)
    const int SM_CONV  = (2 * A_STR + 2 * B_STR) * 4;            // 55296
    const int SM_GRAM  = (2 * A_STR + 2 * L_STR) * 4;            // 55296
    const int SM_ATT   = (2 * T_STR + 2 * B_STR) * 4;            // 53248
    const int SM_FINAL = (A_STR + T_STR + B_STR + B_STR) * 4;    // 54272
    const int SM_SMC   = (256 * 65 + 512) * 4;                   // 68608
    cudaFuncSetAttribute(conv_tc,        cudaFuncAttributeMaxDynamicSharedMemorySize, SM_CONV);
    cudaFuncSetAttribute(gram_tc,        cudaFuncAttributeMaxDynamicSharedMemorySize, SM_GRAM);
    cudaFuncSetAttribute(attended_tc,    cudaFuncAttributeMaxDynamicSharedMemorySize, SM_ATT);
    cudaFuncSetAttribute(final_tc,       cudaFuncAttributeMaxDynamicSharedMemorySize, SM_FINAL);
    cudaFuncSetAttribute(softmax_c_smem, cudaFuncAttributeMaxDynamicSharedMemorySize, SM_SMC);

    const double SIGMA = 1.6;
    const double S_VAL = cbrt(2.0);
    G5 g3 = {}, g5 = {};
    make_gauss1d(3, SIGMA, g3.w);
    make_gauss1d(5, SIGMA * S_VAL, g5.w);

    dim3 gGemm(HWn / 64, Cn / 128, Bn);        // (64, 2, 8)
    dim3 gGram(Cn / 64, Cn / 128, Bn * SPLITK); // (4, 2, 64)

    // 1x1 convs -> K, Q, V (tensor)
    conv_tc<<<gGemm, 256, SM_CONV>>>(x, Wk, bk, gK);
    conv_tc<<<gGemm, 256, SM_CONV>>>(x, Wq, bq, gQ);
    conv_tc<<<gGemm, 256, SM_CONV>>>(x, Wv, bv, gV);

    // softmaxes
    softmax_hw_kernel<<<Bn * Cn, 256>>>(gK, gK, gK, nullptr, 0);
    softmax_c_smem<<<Bn * 64, 256, SM_SMC>>>(gQ);

    // Gaussian pyramid
    gauss_kernel<<<Bn * Cn, 256>>>(x,   gG1, g3, 1);
    gauss_kernel<<<Bn * Cn, 256>>>(gG1, gG2, g5, 2);

    // efficient attention: context (split-K gram + reduce) + attended
    gram_tc<<<gGram, 256, SM_GRAM>>>(gK, gV, gPart);
    reduce_ctx_kernel<<<BCC / 256, 256>>>(gPart, gCtx);
    attended_tc<<<gGemm, 256, SM_ATT>>>(gCtx, gQ, gAtd);

    // channel attention: level 0 (x), level 1 (x-G1), level 2 (G1-G2)
    softmax_hw_kernel<<<Bn * Cn, 256>>>(x, x, gS, nullptr, 0);
    gram_tc<<<gGram, 256, SM_GRAM>>>(gS, x, gPart);
    softmax_rows_accum<<<Bn * Cn, 256>>>(gPart, gAttm, 1);

    softmax_hw_kernel<<<Bn * Cn, 256>>>(x, gG1, gS, gD, 1);
    gram_tc<<<gGram, 256, SM_GRAM>>>(gS, gD, gPart);
    softmax_rows_accum<<<Bn * Cn, 256>>>(gPart, gAttm, 0);

    softmax_hw_kernel<<<Bn * Cn, 256>>>(gG1, gG2, gS, gD, 1);
    gram_tc<<<gGram, 256, SM_GRAM>>>(gS, gD, gPart);
    softmax_rows_accum<<<Bn * Cn, 256>>>(gPart, gAttm, 0);

    // fused: out = w0*(Wr@Atd + br) + w1*(att^T @ Q)
    final_tc<<<gGemm, 256, SM_FINAL>>>(gAtd, gQ, gAttm, Wr, br, wdw, out);
}

// round 5
// speedup vs baseline: 4.3302x; 1.0734x over previous
#include <cuda_runtime.h>
#include <math.h>
#include <stdint.h>

// ---------------------------------------------------------------------------
// EfficientFrequencyAttention  B=8, C=256, H=W=64  — tf32 MMA, cvt-free inner loops
// ---------------------------------------------------------------------------
#define Bn  8
#define Cn  256
#define HWn 4096
#define BCHW (Bn*Cn*HWn)   // 8,388,608
#define BCC  (Bn*Cn*Cn)    // 524,288
#define SPLITK 8

// ----------------------------- scratch (static, no allocation) -------------
__device__ float g_X   [BCHW];   // tf32-rounded copy of x
__device__ float g_K   [BCHW];
__device__ float g_Q   [BCHW];
__device__ float g_V   [BCHW];
__device__ float g_G1  [BCHW];
__device__ float g_G2  [BCHW];
__device__ float g_S   [BCHW];   // per-level softmax (tf32-rounded)
__device__ float g_D   [BCHW];   // per-level raw Laplacian diff (tf32-rounded)
__device__ float g_Atd [BCHW];   // attended (tf32-rounded)
__device__ float g_Ctx [BCC];    // tf32-rounded
__device__ float g_Attm[BCC];    // accumulated channel attention (fp32)
__device__ float g_Part[BCC * SPLITK];
__device__ float g_Wb  [4 * Cn * Cn];  // tf32-rounded Wk,Wq,Wv,Wr

// ----------------------------- helpers -------------------------------------
__device__ __forceinline__ unsigned f2tf(float f) {
    unsigned u;
    asm("cvt.rna.tf32.f32 %0, %1;" : "=r"(u) : "f"(f));
    return u;
}
__device__ __forceinline__ float tfr(float f) { return __uint_as_float(f2tf(f)); }
#define LDU(x) __float_as_uint(x)

__device__ __forceinline__ void mma8(float* c, const unsigned* a, const unsigned* b) {
    asm volatile(
        "mma.sync.aligned.m16n8k8.row.col.f32.tf32.tf32.f32 "
        "{%0,%1,%2,%3},{%4,%5,%6,%7},{%8,%9},{%0,%1,%2,%3};\n"
        : "+f"(c[0]), "+f"(c[1]), "+f"(c[2]), "+f"(c[3])
        : "r"(a[0]), "r"(a[1]), "r"(a[2]), "r"(a[3]),
          "r"(b[0]), "r"(b[1]));
}

__device__ __forceinline__ void cp16(uint32_t dst, const void* src) {
    asm volatile("cp.async.ca.shared.global [%0], [%1], 16;" :: "r"(dst), "l"(src));
}
#define CP_COMMIT() asm volatile("cp.async.commit_group;")
#define CP_WAIT1()  asm volatile("cp.async.wait_group 1;")
#define CP_WAIT0()  asm volatile("cp.async.wait_group 0;")

// smem tile strides (floats)
#define AS_F 4608    // 128 x 36   [m][k] or [n][k]
#define BS_F 4352    // 32  x 136  [k][n] or [k][m]
#define BS64 2304    // 32  x 72   [k][n] (64-wide)

// ---------------------------------------------------------------------------
// conv1x1 (tensor): Y[b,m,n] = sum_k W[m,k]*X[b,k,n] + bias[m]
// block 128(M) x 128(N), warp 32x64, K-chunk 32, double-buffered. grid (32,2,8)
// ---------------------------------------------------------------------------
__global__ __launch_bounds__(256)
void conv_tc(const float* __restrict__ X, const float* __restrict__ Wm,
             const float* __restrict__ bias, float* __restrict__ Y, int roundOut)
{
    extern __shared__ float sm[];
    float* As = sm;              // [2][128][36]
    float* Bs = sm + 2 * AS_F;   // [2][32][136]
    uint32_t sb = (uint32_t)__cvta_generic_to_shared(sm);

    const int b  = blockIdx.z;
    const int m0 = blockIdx.y * 128;
    const int n0 = blockIdx.x * 128;
    const int t  = threadIdx.x;
    const float* Xb = X + (size_t)b * Cn * HWn;

    const int lane = t & 31, warp = t >> 5;
    const int wm = (warp & 3) * 32, wn = (warp >> 2) * 64;
    const int g = lane >> 2, t4 = lane & 3;

    float acc[2][8][4] = {};

    auto issue = [&](int c, int st) {
        const int kc = c * 32;
        #pragma unroll
        for (int i = 0; i < 4; i++) {           // A: 128x32
            int row = (t >> 3) + i * 32, col = (t & 7) * 4;
            cp16(sb + (uint32_t)(st * AS_F + row * 36 + col) * 4,
                 Wm + (size_t)(m0 + row) * Cn + kc + col);
        }
        #pragma unroll
        for (int i = 0; i < 4; i++) {           // B: 32x128
            int row = (t >> 5) + i * 8, col = (t & 31) * 4;
            cp16(sb + (uint32_t)(2 * AS_F + st * BS_F + row * 136 + col) * 4,
                 Xb + (size_t)(kc + row) * HWn + n0 + col);
        }
        CP_COMMIT();
    };

    issue(0, 0);
    const int NC = Cn / 32;  // 8
    for (int c = 0; c < NC; c++) {
        int st = c & 1;
        if (c + 1 < NC) { issue(c + 1, st ^ 1); CP_WAIT1(); }
        else            { CP_WAIT0(); }
        __syncthreads();
        const float* A = As + st * AS_F;
        const float* B = Bs + st * BS_F;
        #pragma unroll
        for (int ks = 0; ks < 4; ks++) {
            const int k8 = ks * 8;
            unsigned af[2][4], bf[8][2];
            #pragma unroll
            for (int mi = 0; mi < 2; mi++) {
                int r = wm + mi * 16 + g;
                af[mi][0] = LDU(A[r * 36 + k8 + t4]);
                af[mi][1] = LDU(A[(r + 8) * 36 + k8 + t4]);
                af[mi][2] = LDU(A[r * 36 + k8 + t4 + 4]);
                af[mi][3] = LDU(A[(r + 8) * 36 + k8 + t4 + 4]);
            }
            #pragma unroll
            for (int ni = 0; ni < 8; ni++) {
                int nb = wn + ni * 8 + g;
                bf[ni][0] = LDU(B[(k8 + t4) * 136 + nb]);
                bf[ni][1] = LDU(B[(k8 + t4 + 4) * 136 + nb]);
            }
            #pragma unroll
            for (int mi = 0; mi < 2; mi++)
                #pragma unroll
                for (int ni = 0; ni < 8; ni++)
                    mma8(acc[mi][ni], af[mi], bf[ni]);
        }
        __syncthreads();
    }

    float* Yb = Y + (size_t)b * Cn * HWn;
    #pragma unroll
    for (int mi = 0; mi < 2; mi++) {
        int r0 = m0 + wm + mi * 16 + g, r1 = r0 + 8;
        float bv0 = bias[r0], bv1 = bias[r1];
        #pragma unroll
        for (int ni = 0; ni < 8; ni++) {
            int col = n0 + wn + ni * 8 + 2 * t4;
            float2 v0 = {acc[mi][ni][0] + bv0, acc[mi][ni][1] + bv0};
            float2 v1 = {acc[mi][ni][2] + bv1, acc[mi][ni][3] + bv1};
            if (roundOut) {
                v0.x = tfr(v0.x); v0.y = tfr(v0.y);
                v1.x = tfr(v1.x); v1.y = tfr(v1.y);
            }
            *(float2*)&Yb[(size_t)r0 * HWn + col] = v0;
            *(float2*)&Yb[(size_t)r1 * HWn + col] = v1;
        }
    }
}

// ---------------------------------------------------------------------------
// gram (tensor, split-K): part[z,m,n] = sum_{k in split} S[b,m,k]*L[b,n,k]
// block 128x128, warp 32x64, K-chunk 32.  grid (2, 2, 64)
// ---------------------------------------------------------------------------
__global__ __launch_bounds__(256)
void gram_tc(const float* __restrict__ S, const float* __restrict__ L,
             float* __restrict__ part)
{
    extern __shared__ float sm[];
    float* As = sm;              // [2][128][36]  S[m][k]
    float* Ls = sm + 2 * AS_F;   // [2][128][36]  L[n][k]
    uint32_t sb = (uint32_t)__cvta_generic_to_shared(sm);

    const int z = blockIdx.z, b = z >> 3, s = z & 7;
    const int m0 = blockIdx.y * 128;
    const int n0 = blockIdx.x * 128;
    const int kb = s * (HWn / SPLITK);
    const int t = threadIdx.x;
    const float* Sb = S + (size_t)b * Cn * HWn;
    const float* Lb = L + (size_t)b * Cn * HWn;

    const int lane = t & 31, warp = t >> 5;
    const int wm = (warp & 3) * 32, wn = (warp >> 2) * 64;
    const int g = lane >> 2, t4 = lane & 3;

    float acc[2][8][4] = {};

    auto issue = [&](int c, int st) {
        const int kc = kb + c * 32;
        #pragma unroll
        for (int i = 0; i < 4; i++) {
            int row = (t >> 3) + i * 32, col = (t & 7) * 4;
            cp16(sb + (uint32_t)(st * AS_F + row * 36 + col) * 4,
                 Sb + (size_t)(m0 + row) * HWn + kc + col);
            cp16(sb + (uint32_t)(2 * AS_F + st * AS_F + row * 36 + col) * 4,
                 Lb + (size_t)(n0 + row) * HWn + kc + col);
        }
        CP_COMMIT();
    };

    issue(0, 0);
    const int NC = (HWn / SPLITK) / 32;  // 16
    for (int c = 0; c < NC; c++) {
        int st = c & 1;
        if (c + 1 < NC) { issue(c + 1, st ^ 1); CP_WAIT1(); }
        else            { CP_WAIT0(); }
        __syncthreads();
        const float* A  = As + st * AS_F;
        const float* Lt = Ls + st * AS_F;
        #pragma unroll
        for (int ks = 0; ks < 4; ks++) {
            const int k8 = ks * 8;
            unsigned af[2][4], bf[8][2];
            #pragma unroll
            for (int mi = 0; mi < 2; mi++) {
                int r = wm + mi * 16 + g;
                af[mi][0] = LDU(A[r * 36 + k8 + t4]);
                af[mi][1] = LDU(A[(r + 8) * 36 + k8 + t4]);
                af[mi][2] = LDU(A[r * 36 + k8 + t4 + 4]);
                af[mi][3] = LDU(A[(r + 8) * 36 + k8 + t4 + 4]);
            }
            #pragma unroll
            for (int ni = 0; ni < 8; ni++) {
                int nb = wn + ni * 8 + g;
                bf[ni][0] = LDU(Lt[nb * 36 + k8 + t4]);
                bf[ni][1] = LDU(Lt[nb * 36 + k8 + t4 + 4]);
            }
            #pragma unroll
            for (int mi = 0; mi < 2; mi++)
                #pragma unroll
                for (int ni = 0; ni < 8; ni++)
                    mma8(acc[mi][ni], af[mi], bf[ni]);
        }
        __syncthreads();
    }

    float* P = part + (size_t)z * Cn * Cn;
    #pragma unroll
    for (int mi = 0; mi < 2; mi++) {
        int r0 = m0 + wm + mi * 16 + g, r1 = r0 + 8;
        #pragma unroll
        for (int ni = 0; ni < 8; ni++) {
            int col = n0 + wn + ni * 8 + 2 * t4;
            *(float2*)&P[(size_t)r0 * Cn + col] = make_float2(acc[mi][ni][0], acc[mi][ni][1]);
            *(float2*)&P[(size_t)r1 * Cn + col] = make_float2(acc[mi][ni][2], acc[mi][ni][3]);
        }
    }
}

// ---------------------------------------------------------------------------
// attended (tensor): out[b,m,n] = sum_k ctx[b,k,m] * Q[b,k,n]   grid (32,2,8)
// output tf32-rounded.
// ---------------------------------------------------------------------------
__global__ __launch_bounds__(256)
void attended_tc(const float* __restrict__ ctx, const float* __restrict__ Q,
                 float* __restrict__ out)
{
    extern __shared__ float sm[];
    float* Cs = sm;              // [2][32][136]  ctx[k][m]
    float* Bs = sm + 2 * BS_F;   // [2][32][136]  Q[k][n]
    uint32_t sb = (uint32_t)__cvta_generic_to_shared(sm);

    const int b  = blockIdx.z;
    const int m0 = blockIdx.y * 128;
    const int n0 = blockIdx.x * 128;
    const int t  = threadIdx.x;
    const float* cb = ctx + (size_t)b * Cn * Cn;
    const float* qb = Q   + (size_t)b * Cn * HWn;

    const int lane = t & 31, warp = t >> 5;
    const int wm = (warp & 3) * 32, wn = (warp >> 2) * 64;
    const int g = lane >> 2, t4 = lane & 3;

    float acc[2][8][4] = {};

    auto issue = [&](int c, int st) {
        const int kc = c * 32;
        #pragma unroll
        for (int i = 0; i < 4; i++) {
            int row = (t >> 5) + i * 8, col = (t & 31) * 4;
            cp16(sb + (uint32_t)(st * BS_F + row * 136 + col) * 4,
                 cb + (size_t)(kc + row) * Cn + m0 + col);
            cp16(sb + (uint32_t)(2 * BS_F + st * BS_F + row * 136 + col) * 4,
                 qb + (size_t)(kc + row) * HWn + n0 + col);
        }
        CP_COMMIT();
    };

    issue(0, 0);
    const int NC = Cn / 32;  // 8
    for (int c = 0; c < NC; c++) {
        int st = c & 1;
        if (c + 1 < NC) { issue(c + 1, st ^ 1); CP_WAIT1(); }
        else            { CP_WAIT0(); }
        __syncthreads();
        const float* A = Cs + st * BS_F;
        const float* B = Bs + st * BS_F;
        #pragma unroll
        for (int ks = 0; ks < 4; ks++) {
            const int k8 = ks * 8;
            unsigned af[2][4], bf[8][2];
            #pragma unroll
            for (int mi = 0; mi < 2; mi++) {
                int r = wm + mi * 16 + g;
                af[mi][0] = LDU(A[(k8 + t4) * 136 + r]);
                af[mi][1] = LDU(A[(k8 + t4) * 136 + r + 8]);
                af[mi][2] = LDU(A[(k8 + t4 + 4) * 136 + r]);
                af[mi][3] = LDU(A[(k8 + t4 + 4) * 136 + r + 8]);
            }
            #pragma unroll
            for (int ni = 0; ni < 8; ni++) {
                int nb = wn + ni * 8 + g;
                bf[ni][0] = LDU(B[(k8 + t4) * 136 + nb]);
                bf[ni][1] = LDU(B[(k8 + t4 + 4) * 136 + nb]);
            }
            #pragma unroll
            for (int mi = 0; mi < 2; mi++)
                #pragma unroll
                for (int ni = 0; ni < 8; ni++)
                    mma8(acc[mi][ni], af[mi], bf[ni]);
        }
        __syncthreads();
    }

    float* ob = out + (size_t)b * Cn * HWn;
    #pragma unroll
    for (int mi = 0; mi < 2; mi++) {
        int r0 = m0 + wm + mi * 16 + g, r1 = r0 + 8;
        #pragma unroll
        for (int ni = 0; ni < 8; ni++) {
            int col = n0 + wn + ni * 8 + 2 * t4;
            *(float2*)&ob[(size_t)r0 * HWn + col] =
                make_float2(tfr(acc[mi][ni][0]), tfr(acc[mi][ni][1]));
            *(float2*)&ob[(size_t)r1 * HWn + col] =
                make_float2(tfr(acc[mi][ni][2]), tfr(acc[mi][ni][3]));
        }
    }
}

// ---------------------------------------------------------------------------
// fused final: out = w0*(Wr@Atd + br) + w1*(att^T @ Q).  128m x 64n. grid (64,2,8)
// Wr/Atd/Q pre-rounded (raw loads); att fp32 (cvt in loop).
// ---------------------------------------------------------------------------
__global__ __launch_bounds__(256)
void final_tc(const float* __restrict__ Atd, const float* __restrict__ Q,
              const float* __restrict__ att, const float* __restrict__ Wr,
              const float* __restrict__ br, const float* __restrict__ wdw,
              float* __restrict__ out)
{
    extern __shared__ float sm[];
    float* As  = sm;                         // [128][36]  Wr
    float* Ts  = sm + AS_F;                  // [32][136]  att (k,m)
    float* B1s = sm + AS_F + BS_F;           // [32][72]   Atd
    float* B2s = sm + AS_F + BS_F + BS64;    // [32][72]   Q
    uint32_t sb = (uint32_t)__cvta_generic_to_shared(sm);

    const int b  = blockIdx.z;
    const int m0 = blockIdx.y * 128;
    const int n0 = blockIdx.x * 64;
    const int t  = threadIdx.x;
    const float* ab   = Atd + (size_t)b * Cn * HWn;
    const float* qb   = Q   + (size_t)b * Cn * HWn;
    const float* attb = att + (size_t)b * Cn * Cn;

    const int lane = t & 31, warp = t >> 5;
    const int wm = (warp >> 1) * 32, wn = (warp & 1) * 32;
    const int g = lane >> 2, t4 = lane & 3;

    float acc1[2][4][4] = {};
    float acc2[2][4][4] = {};

    const int NC = Cn / 32;  // 8
    for (int c = 0; c < NC; c++) {
        const int kc = c * 32;
        if (c > 0) __syncthreads();
        #pragma unroll
        for (int i = 0; i < 4; i++) { // Wr: 128x32
            int row = (t >> 3) + i * 32, col = (t & 7) * 4;
            cp16(sb + (uint32_t)(row * 36 + col) * 4,
                 Wr + (size_t)(m0 + row) * Cn + kc + col);
        }
        #pragma unroll
        for (int i = 0; i < 4; i++) { // att: 32(k)x128(m)
            int row = (t >> 5) + i * 8, col = (t & 31) * 4;
            cp16(sb + (uint32_t)(AS_F + row * 136 + col) * 4,
                 attb + (size_t)(kc + row) * Cn + m0 + col);
        }
        #pragma unroll
        for (int i = 0; i < 2; i++) { // Atd & Q: 32x64
            int row = (t >> 4) + i * 16, col = (t & 15) * 4;
            cp16(sb + (uint32_t)(AS_F + BS_F + row * 72 + col) * 4,
                 ab + (size_t)(kc + row) * HWn + n0 + col);
            cp16(sb + (uint32_t)(AS_F + BS_F + BS64 + row * 72 + col) * 4,
                 qb + (size_t)(kc + row) * HWn + n0 + col);
        }
        CP_COMMIT();
        CP_WAIT0();
        __syncthreads();

        #pragma unroll
        for (int ks = 0; ks < 4; ks++) {
            const int k8 = ks * 8;
            unsigned a1f[2][4], a2f[2][4], b1f[4][2], b2f[4][2];
            #pragma unroll
            for (int mi = 0; mi < 2; mi++) {
                int r = wm + mi * 16 + g;
                a1f[mi][0] = LDU(As[r * 36 + k8 + t4]);
                a1f[mi][1] = LDU(As[(r + 8) * 36 + k8 + t4]);
                a1f[mi][2] = LDU(As[r * 36 + k8 + t4 + 4]);
                a1f[mi][3] = LDU(As[(r + 8) * 36 + k8 + t4 + 4]);
                a2f[mi][0] = f2tf(Ts[(k8 + t4) * 136 + r]);
                a2f[mi][1] = f2tf(Ts[(k8 + t4) * 136 + r + 8]);
                a2f[mi][2] = f2tf(Ts[(k8 + t4 + 4) * 136 + r]);
                a2f[mi][3] = f2tf(Ts[(k8 + t4 + 4) * 136 + r + 8]);
            }
            #pragma unroll
            for (int ni = 0; ni < 4; ni++) {
                int nb = wn + ni * 8 + g;
                b1f[ni][0] = LDU(B1s[(k8 + t4) * 72 + nb]);
                b1f[ni][1] = LDU(B1s[(k8 + t4 + 4) * 72 + nb]);
                b2f[ni][0] = LDU(B2s[(k8 + t4) * 72 + nb]);
                b2f[ni][1] = LDU(B2s[(k8 + t4 + 4) * 72 + nb]);
            }
            #pragma unroll
            for (int mi = 0; mi < 2; mi++)
                #pragma unroll
                for (int ni = 0; ni < 4; ni++) {
                    mma8(acc1[mi][ni], a1f[mi], b1f[ni]);
                    mma8(acc2[mi][ni], a2f[mi], b2f[ni]);
                }
        }
    }

    float* ob = out + (size_t)b * Cn * HWn;
    #pragma unroll
    for (int mi = 0; mi < 2; mi++) {
        int r0 = m0 + wm + mi * 16 + g, r1 = r0 + 8;
        float w00 = wdw[2 * r0], w01 = wdw[2 * r0 + 1], bb0 = br[r0];
        float w10 = wdw[2 * r1], w11 = wdw[2 * r1 + 1], bb1 = br[r1];
        #pragma unroll
        for (int ni = 0; ni < 4; ni++) {
            int col = n0 + wn + ni * 8 + 2 * t4;
            float2 v0, v1;
            v0.x = w00 * (acc1[mi][ni][0] + bb0) + w01 * acc2[mi][ni][0];
            v0.y = w00 * (acc1[mi][ni][1] + bb0) + w01 * acc2[mi][ni][1];
            v1.x = w10 * (acc1[mi][ni][2] + bb1) + w11 * acc2[mi][ni][2];
            v1.y = w10 * (acc1[mi][ni][3] + bb1) + w11 * acc2[mi][ni][3];
            *(float2*)&ob[(size_t)r0 * HWn + col] = v0;
            *(float2*)&ob[(size_t)r1 * HWn + col] = v1;
        }
    }
}

// ---------------------------------------------------------------------------
// tf32 rounding copy
// ---------------------------------------------------------------------------
__global__ __launch_bounds__(256)
void round_kernel(const float* __restrict__ src, float* __restrict__ dst, int n)
{
    int i = blockIdx.x * 256 + threadIdx.x;
    if (i < n) dst[i] = tfr(src[i]);
}

// ---------------------------------------------------------------------------
// softmax over HW per (b,c) row; optional (A - Bm); out & raw tf32-rounded.
// ---------------------------------------------------------------------------
__global__ __launch_bounds__(256)
void softmax_hw_kernel(const float* __restrict__ A, const float* __restrict__ Bm,
                       float* __restrict__ out, float* __restrict__ raw, int hasB)
{
    __shared__ float red[256];
    const size_t base = (size_t)blockIdx.x * HWn;
    const int t = threadIdx.x;

    float v[16];
    float m = -INFINITY;
    #pragma unroll
    for (int i = 0; i < 16; i++) {
        size_t idx = base + t + i * 256;
        float a = A[idx];
        if (hasB) a -= Bm[idx];
        if (raw) raw[idx] = tfr(a);
        v[i] = a;
        m = fmaxf(m, a);
    }
    red[t] = m; __syncthreads();
    for (int s = 128; s > 0; s >>= 1) {
        if (t < s) red[t] = fmaxf(red[t], red[t + s]);
        __syncthreads();
    }
    m = red[0]; __syncthreads();

    float sum = 0.f;
    #pragma unroll
    for (int i = 0; i < 16; i++) { v[i] = expf(v[i] - m); sum += v[i]; }
    red[t] = sum; __syncthreads();
    for (int s = 128; s > 0; s >>= 1) {
        if (t < s) red[t] += red[t + s];
        __syncthreads();
    }
    float inv = 1.0f / red[0];
    #pragma unroll
    for (int i = 0; i < 16; i++) out[base + t + i * 256] = tfr(v[i] * inv);
}

// ---------------------------------------------------------------------------
// softmax over channel axis (256), smem-cached; output tf32-rounded.
// ---------------------------------------------------------------------------
__global__ __launch_bounds__(256)
void softmax_c_smem(float* __restrict__ Q)
{
    extern __shared__ float sm[];
    const int P = 65;
    float* red = sm + 256 * P;
    const int blk = blockIdx.x;
    const int b = blk >> 6, n0 = (blk & 63) * 64;
    float* base = Q + (size_t)b * Cn * HWn + n0;
    const int t = threadIdx.x, nl = t & 63, cs = t >> 6;

    #pragma unroll 4
    for (int i = 0; i < 64; i++) {
        int c = cs * 64 + i;
        sm[c * P + nl] = base[(size_t)c * HWn + nl];
    }
    __syncthreads();
    float m = -INFINITY;
    #pragma unroll 4
    for (int i = 0; i < 64; i++) m = fmaxf(m, sm[(cs * 64 + i) * P + nl]);
    red[cs * 64 + nl] = m;
    __syncthreads();
    if (t < 64)
        red[t] = fmaxf(fmaxf(red[t], red[64 + t]), fmaxf(red[128 + t], red[192 + t]));
    __syncthreads();
    m = red[nl];
    __syncthreads();
    float s = 0.f;
    #pragma unroll 4
    for (int i = 0; i < 64; i++) {
        int c = cs * 64 + i;
        float e = expf(sm[c * P + nl] - m);
        sm[c * P + nl] = e;
        s += e;
    }
    red[cs * 64 + nl] = s;
    __syncthreads();
    if (t < 64) red[t] = red[t] + red[64 + t] + red[128 + t] + red[192 + t];
    __syncthreads();
    float inv = 1.0f / red[nl];
    #pragma unroll 4
    for (int i = 0; i < 64; i++) {
        int c = cs * 64 + i;
        base[(size_t)c * HWn + nl] = tfr(sm[c * P + nl] * inv);
    }
}

// ---------------------------------------------------------------------------
// ctx reduce (tf32-rounded output)
// ---------------------------------------------------------------------------
__global__ __launch_bounds__(256)
void reduce_ctx_kernel(const float* __restrict__ part, float* __restrict__ ctx)
{
    const int e = blockIdx.x * 256 + threadIdx.x;
    const int b = e >> 16, r = e & 65535;
    float v = 0.f;
    #pragma unroll
    for (int s = 0; s < SPLITK; s++)
        v += part[((size_t)(b * SPLITK + s) << 16) + r];
    ctx[e] = tfr(v);
}

// ---------------------------------------------------------------------------
// row softmax (256) of split-K gram partials, accumulate into att (fp32)
// ---------------------------------------------------------------------------
__global__ __launch_bounds__(256)
void softmax_rows_accum(const float* __restrict__ part, float* __restrict__ att, int init)
{
    __shared__ float red[256];
    const int row = blockIdx.x;
    const int b = row >> 8, i = row & 255;
    const int t = threadIdx.x;

    float v = 0.f;
    size_t base = ((size_t)b * SPLITK << 16) + (size_t)i * Cn + t;
    #pragma unroll
    for (int s = 0; s < SPLITK; s++) v += part[base + ((size_t)s << 16)];

    red[t] = v; __syncthreads();
    for (int s = 128; s > 0; s >>= 1) {
        if (t < s) red[t] = fmaxf(red[t], red[t + s]);
        __syncthreads();
    }
    float m = red[0]; __syncthreads();
    float e = expf(v - m);
    red[t] = e; __syncthreads();
    for (int s = 128; s > 0; s >>= 1) {
        if (t < s) red[t] += red[t + s];
        __syncthreads();
    }
    float r = e / red[0];
    size_t o = (size_t)row * Cn + t;
    att[o] = init ? r : (att[o] + r);
}

// ---------------------------------------------------------------------------
// separable depthwise Gaussian, 'SAME' zero padding; one block per image
// ---------------------------------------------------------------------------
struct G5 { float w[5]; };

__global__ __launch_bounds__(256)
void gauss_kernel(const float* __restrict__ in, float* __restrict__ out, G5 g, int r)
{
    __shared__ float s_in[64][65];
    __shared__ float s_h [64][65];

    const int img = blockIdx.x;
    const int t = threadIdx.x;
    const float* ip = in + (size_t)img * HWn;

    #pragma unroll
    for (int i = 0; i < 16; i++) {
        int px = t + i * 256;
        s_in[px >> 6][px & 63] = ip[px];
    }
    __syncthreads();
    #pragma unroll
    for (int i = 0; i < 16; i++) {
        int px = t + i * 256;
        int y = px >> 6, x = px & 63;
        float acc = 0.f;
        for (int d = -r; d <= r; d++) {
            int xx = x + d;
            if (xx >= 0 && xx < 64) acc += g.w[d + r] * s_in[y][xx];
        }
        s_h[y][x] = acc;
    }
    __syncthreads();
    float* op = out + (size_t)img * HWn;
    #pragma unroll
    for (int i = 0; i < 16; i++) {
        int px = t + i * 256;
        int y = px >> 6, x = px & 63;
        float acc = 0.f;
        for (int d = -r; d <= r; d++) {
            int yy = y + d;
            if (yy >= 0 && yy < 64) acc += g.w[d + r] * s_h[yy][x];
        }
        op[px] = acc;
    }
}

// ---------------------------------------------------------------------------
// host
// ---------------------------------------------------------------------------
static void make_gauss1d(int ksize, double sigma, float* w)
{
    double g[5], s = 0.0;
    for (int i = 0; i < ksize; i++) {
        double d = (double)i - (ksize - 1) / 2.0;
        g[i] = exp(-(d * d) / (2.0 * sigma * sigma));
        s += g[i];
    }
    for (int i = 0; i < ksize; i++) w[i] = (float)(g[i] / s);
}

extern "C" void kernel_launch(void* const* d_in, const int* in_sizes, int n_in,
                              void* d_out, int out_size)
{
    (void)in_sizes; (void)n_in; (void)out_size;
    const float* x   = (const float*)d_in[0];
    const float* Wk  = (const float*)d_in[1];
    const float* bk  = (const float*)d_in[2];
    const float* Wq  = (const float*)d_in[3];
    const float* bq  = (const float*)d_in[4];
    const float* Wv  = (const float*)d_in[5];
    const float* bv  = (const float*)d_in[6];
    const float* Wr  = (const float*)d_in[7];
    const float* br  = (const float*)d_in[8];
    const float* wdw = (const float*)d_in[9];
    float* out = (float*)d_out;

    float *gX, *gK, *gQ, *gV, *gG1, *gG2, *gS, *gD, *gAtd, *gCtx, *gAttm, *gPart, *gWb;
    cudaGetSymbolAddress((void**)&gX,    g_X);
    cudaGetSymbolAddress((void**)&gK,    g_K);
    cudaGetSymbolAddress((void**)&gQ,    g_Q);
    cudaGetSymbolAddress((void**)&gV,    g_V);
    cudaGetSymbolAddress((void**)&gG1,   g_G1);
    cudaGetSymbolAddress((void**)&gG2,   g_G2);
    cudaGetSymbolAddress((void**)&gS,    g_S);
    cudaGetSymbolAddress((void**)&gD,    g_D);
    cudaGetSymbolAddress((void**)&gAtd,  g_Atd);
    cudaGetSymbolAddress((void**)&gCtx,  g_Ctx);
    cudaGetSymbolAddress((void**)&gAttm, g_Attm);
    cudaGetSymbolAddress((void**)&gPart, g_Part);
    cudaGetSymbolAddress((void**)&gWb,   g_Wb);

    const int SM_CONV  = (2 * AS_F + 2 * BS_F) * 4;              // 71680
    const int SM_GRAM  = (4 * AS_F) * 4;                         // 73728
    const int SM_ATT   = (4 * BS_F) * 4;                         // 69632
    const int SM_FINAL = (AS_F + BS_F + 2 * BS64) * 4;           // 54272
    const int SM_SMC   = (256 * 65 + 512) * 4;                   // 68608
    cudaFuncSetAttribute(conv_tc,        cudaFuncAttributeMaxDynamicSharedMemorySize, SM_CONV);
    cudaFuncSetAttribute(gram_tc,        cudaFuncAttributeMaxDynamicSharedMemorySize, SM_GRAM);
    cudaFuncSetAttribute(attended_tc,    cudaFuncAttributeMaxDynamicSharedMemorySize, SM_ATT);
    cudaFuncSetAttribute(final_tc,       cudaFuncAttributeMaxDynamicSharedMemorySize, SM_FINAL);
    cudaFuncSetAttribute(softmax_c_smem, cudaFuncAttributeMaxDynamicSharedMemorySize, SM_SMC);

    const double SIGMA = 1.6;
    const double S_VAL = cbrt(2.0);
    G5 g3 = {}, g5 = {};
    make_gauss1d(3, SIGMA, g3.w);
    make_gauss1d(5, SIGMA * S_VAL, g5.w);

    dim3 gGemm(HWn / 128, Cn / 128, Bn);          // (32, 2, 8)
    dim3 gGram(Cn / 128, Cn / 128, Bn * SPLITK);  // (2, 2, 64)
    dim3 gFin (HWn / 64, Cn / 128, Bn);           // (64, 2, 8)

    // pre-round x and weights to tf32 (bitwise-identical to cvt-at-mma)
    round_kernel<<<BCHW / 256, 256>>>(x, gX, BCHW);
    round_kernel<<<Cn * Cn / 256, 256>>>(Wk, gWb + 0 * Cn * Cn, Cn * Cn);
    round_kernel<<<Cn * Cn / 256, 256>>>(Wq, gWb + 1 * Cn * Cn, Cn * Cn);
    round_kernel<<<Cn * Cn / 256, 256>>>(Wv, gWb + 2 * Cn * Cn, Cn * Cn);
    round_kernel<<<Cn * Cn / 256, 256>>>(Wr, gWb + 3 * Cn * Cn, Cn * Cn);

    // 1x1 convs -> K, Q (fp32 out, rounded downstream), V (rounded out)
    conv_tc<<<gGemm, 256, SM_CONV>>>(gX, gWb + 0 * Cn * Cn, bk, gK, 0);
    conv_tc<<<gGemm, 256, SM_CONV>>>(gX, gWb + 1 * Cn * Cn, bq, gQ, 0);
    conv_tc<<<gGemm, 256, SM_CONV>>>(gX, gWb + 2 * Cn * Cn, bv, gV, 1);

    // softmaxes (tf32-rounded outputs)
    softmax_hw_kernel<<<Bn * Cn, 256>>>(gK, gK, gK, nullptr, 0);
    softmax_c_smem<<<Bn * 64, 256, SM_SMC>>>(gQ);

    // Gaussian pyramid (fp32; rounded at diff/softmax stage)
    gauss_kernel<<<Bn * Cn, 256>>>(x,   gG1, g3, 1);
    gauss_kernel<<<Bn * Cn, 256>>>(gG1, gG2, g5, 2);

    // efficient attention
    gram_tc<<<gGram, 256, SM_GRAM>>>(gK, gV, gPart);
    reduce_ctx_kernel<<<BCC / 256, 256>>>(gPart, gCtx);
    attended_tc<<<gGemm, 256, SM_ATT>>>(gCtx, gQ, gAtd);

    // channel attention: level 0 (x), level 1 (x-G1), level 2 (G1-G2)
    softmax_hw_kernel<<<Bn * Cn, 256>>>(x, x, gS, nullptr, 0);
    gram_tc<<<gGram, 256, SM_GRAM>>>(gS, gX, gPart);
    softmax_rows_accum<<<Bn * Cn, 256>>>(gPart, gAttm, 1);

    softmax_hw_kernel<<<Bn * Cn, 256>>>(x, gG1, gS, gD, 1);
    gram_tc<<<gGram, 256, SM_GRAM>>>(gS, gD, gPart);
    softmax_rows_accum<<<Bn * Cn, 256>>>(gPart, gAttm, 0);

    softmax_hw_kernel<<<Bn * Cn, 256>>>(gG1, gG2, gS, gD, 1);
    gram_tc<<<gGram, 256, SM_GRAM>>>(gS, gD, gPart);
    softmax_rows_accum<<<Bn * Cn, 256>>>(gPart, gAttm, 0);

    // fused final
    final_tc<<<gFin, 256, SM_FINAL>>>(gAtd, gQ, gAttm, gWb + 3 * Cn * Cn, br, wdw, out);
}